// round 1
// baseline (speedup 1.0000x reference)
#include <cuda_runtime.h>
#include <cstdint>
#include <cstddef>

// ---------------------------------------------------------------------------
// GAT 3-layer + mean/max pool + linear readout, fp32.
// Softmax fusion: out[dst] = (sum_e exp(e)*h[src]) / (sum_e exp(e) + 1e-16)
// so no per-edge alpha storage, one max pass + one accumulate pass per layer.
// ---------------------------------------------------------------------------

#define NMAX 50000
#define GMAX 128

__device__ float g_bufP[NMAX * 256];   // GEMM output h  (max 51.2 MB)
__device__ float g_bufQ[NMAX * 256];   // aggregate output / next layer input
__device__ float g_ssrc[NMAX * 4];
__device__ float g_sdst[NMAX * 4];
__device__ float g_max [NMAX * 4];
__device__ float g_denom[NMAX * 4];
__device__ float g_pooled[GMAX * 512];

// ---------------------------------------------------------------------------
// SGEMM: C[M,N] = A[M,K] @ B[K,N], row-major, fp32.
// 64x64 block tile, BK=16, 256 threads, 4x4 microtile.
// N,K are multiples of 64/16 here (128 or 256); only M needs guarding.
// ---------------------------------------------------------------------------
__global__ void k_sgemm(const float* __restrict__ A, const float* __restrict__ B,
                        float* __restrict__ C, int M, int N, int K) {
    __shared__ float As[16][64 + 1];   // transposed, padded vs bank conflicts
    __shared__ float Bs[16][64];
    int tid = threadIdx.x;
    int tx = tid & 15, ty = tid >> 4;
    int rowBase = blockIdx.y * 64;
    int colBase = blockIdx.x * 64;

    int aRow = rowBase + (tid >> 2);     // 64 rows, 4 threads per row
    int aColGrp = (tid & 3) * 4;         // 4 consecutive k per thread
    int bRow = tid >> 4;                 // 16 rows, 16 threads per row
    int bCol = (tid & 15) * 4;

    float acc[4][4] = {};

    for (int k0 = 0; k0 < K; k0 += 16) {
        float4 av = make_float4(0.f, 0.f, 0.f, 0.f);
        if (aRow < M)
            av = *reinterpret_cast<const float4*>(A + (size_t)aRow * K + k0 + aColGrp);
        As[aColGrp + 0][tid >> 2] = av.x;
        As[aColGrp + 1][tid >> 2] = av.y;
        As[aColGrp + 2][tid >> 2] = av.z;
        As[aColGrp + 3][tid >> 2] = av.w;

        float4 bv = *reinterpret_cast<const float4*>(
            B + (size_t)(k0 + bRow) * N + colBase + bCol);
        *reinterpret_cast<float4*>(&Bs[bRow][bCol]) = bv;
        __syncthreads();

        #pragma unroll
        for (int kk = 0; kk < 16; kk++) {
            float ra[4];
            #pragma unroll
            for (int j = 0; j < 4; j++) ra[j] = As[kk][ty * 4 + j];
            float4 rbv = *reinterpret_cast<const float4*>(&Bs[kk][tx * 4]);
            float rb[4] = {rbv.x, rbv.y, rbv.z, rbv.w};
            #pragma unroll
            for (int i = 0; i < 4; i++)
                #pragma unroll
                for (int j = 0; j < 4; j++)
                    acc[i][j] += ra[i] * rb[j];
        }
        __syncthreads();
    }

    #pragma unroll
    for (int i = 0; i < 4; i++) {
        int r = rowBase + ty * 4 + i;
        if (r < M) {
            float4 o = make_float4(acc[i][0], acc[i][1], acc[i][2], acc[i][3]);
            *reinterpret_cast<float4*>(C + (size_t)r * N + colBase + tx * 4) = o;
        }
    }
}

// ---------------------------------------------------------------------------
__global__ void k_init(float* __restrict__ acc, float* __restrict__ denom,
                       float* __restrict__ mx, int nC4, int nH) {
    int i = blockIdx.x * blockDim.x + threadIdx.x;
    if (i < nC4) reinterpret_cast<float4*>(acc)[i] = make_float4(0.f, 0.f, 0.f, 0.f);
    if (i < nH) { denom[i] = 0.f; mx[i] = -3.0e38f; }
}

// ---------------------------------------------------------------------------
// Per-(node,head) attention scores: s = <h[n,head,:], a[head,:]>. Warp per pair.
// ---------------------------------------------------------------------------
__global__ void k_scores(const float* __restrict__ h, const float* __restrict__ asrc,
                         const float* __restrict__ adst, float* __restrict__ ssrc,
                         float* __restrict__ sdst, int Nn, int Fo) {
    int w = (blockIdx.x * blockDim.x + threadIdx.x) >> 5;
    int lane = threadIdx.x & 31;
    if (w >= Nn * 4) return;
    int head = w & 3, node = w >> 2;
    int C = Fo * 4;
    const float* hp = h + (size_t)node * C + head * Fo;
    const float* as = asrc + head * Fo;
    const float* ad = adst + head * Fo;
    float s1 = 0.f, s2 = 0.f;
    for (int f = lane; f < Fo; f += 32) {
        float v = hp[f];
        s1 += v * as[f];
        s2 += v * ad[f];
    }
    #pragma unroll
    for (int o = 16; o; o >>= 1) {
        s1 += __shfl_xor_sync(0xffffffffu, s1, o);
        s2 += __shfl_xor_sync(0xffffffffu, s2, o);
    }
    if (lane == 0) { ssrc[w] = s1; sdst[w] = s2; }
}

// ---------------------------------------------------------------------------
__device__ __forceinline__ float lrelu(float v) { return v > 0.f ? v : 0.2f * v; }

__device__ __forceinline__ void atomicMaxF(float* a, float v) {
    if (v >= 0.f) atomicMax(reinterpret_cast<int*>(a), __float_as_int(v));
    else          atomicMin(reinterpret_cast<unsigned int*>(a), __float_as_uint(v));
}

// Thread per edge (incl. self-loops): segment max of leaky_relu scores.
__global__ void k_edgemax(const int* __restrict__ esrc, const int* __restrict__ edst,
                          const float* __restrict__ ssrc, const float* __restrict__ sdst,
                          float* __restrict__ mx, int E, int Etot) {
    int e = blockIdx.x * blockDim.x + threadIdx.x;
    if (e >= Etot) return;
    int s, d;
    if (e < E) { s = esrc[e]; d = edst[e]; } else { s = d = e - E; }
    float4 a = *reinterpret_cast<const float4*>(ssrc + s * 4);
    float4 b = *reinterpret_cast<const float4*>(sdst + d * 4);
    atomicMaxF(mx + d * 4 + 0, lrelu(a.x + b.x));
    atomicMaxF(mx + d * 4 + 1, lrelu(a.y + b.y));
    atomicMaxF(mx + d * 4 + 2, lrelu(a.z + b.z));
    atomicMaxF(mx + d * 4 + 3, lrelu(a.w + b.w));
}

// ---------------------------------------------------------------------------
// Warp per edge: acc[dst] += exp(e - max)*h[src], denom[dst] += exp(e - max).
// Vector red.global.add.v4.f32 cuts atomic issue count 4x.
// ---------------------------------------------------------------------------
__global__ void k_edgeacc(const int* __restrict__ esrc, const int* __restrict__ edst,
                          const float* __restrict__ ssrc, const float* __restrict__ sdst,
                          const float* __restrict__ mx, const float* __restrict__ h,
                          float* __restrict__ acc, float* __restrict__ denom,
                          int E, int Etot, int C, int Fo) {
    int w = (blockIdx.x * blockDim.x + threadIdx.x) >> 5;
    int lane = threadIdx.x & 31;
    if (w >= Etot) return;
    int s, d;
    if (w < E) { s = esrc[w]; d = edst[w]; } else { s = d = w - E; }

    float ex = 0.f;
    if (lane < 4) {
        float v = lrelu(ssrc[s * 4 + lane] + sdst[d * 4 + lane]);
        ex = __expf(v - mx[d * 4 + lane]);
        atomicAdd(denom + d * 4 + lane, ex);
    }

    const float4* hp = reinterpret_cast<const float4*>(h + (size_t)s * C);
    float* ap = acc + (size_t)d * C;
    int fo4 = Fo >> 2;          // float4s per head
    int c4  = C  >> 2;          // 32 (layer0) or 64
    for (int i = lane; i < c4; i += 32) {
        float4 v = hp[i];
        float exh = __shfl_sync(0xffffffffu, ex, i / fo4);
        v.x *= exh; v.y *= exh; v.z *= exh; v.w *= exh;
        asm volatile("red.global.add.v4.f32 [%0], {%1,%2,%3,%4};"
                     :: "l"(ap + i * 4), "f"(v.x), "f"(v.y), "f"(v.z), "f"(v.w)
                     : "memory");
    }
}

// ---------------------------------------------------------------------------
__global__ void k_finalize(float* __restrict__ acc, const float* __restrict__ denom,
                           const float* __restrict__ b, int Nn, int C, int Fo) {
    int i = blockIdx.x * blockDim.x + threadIdx.x;
    if (i >= Nn * C) return;
    int n = i / C, c = i - n * C;
    int head = c / Fo;
    float v = acc[i] / (denom[n * 4 + head] + 1e-16f) + b[c];
    acc[i] = v > 0.f ? v : 0.f;
}

// ---------------------------------------------------------------------------
// Per-graph mean/max pool over sorted batch_index.
// grid = (128 graphs, 2 feature halves), block = 128 threads (one per feature).
// ---------------------------------------------------------------------------
__global__ void k_pool(const float* __restrict__ h, const int* __restrict__ batch,
                       float* __restrict__ pooled, int Nn) {
    int g = blockIdx.x;
    int f = blockIdx.y * 128 + threadIdx.x;   // 0..255

    int lo = 0, hi = Nn;
    while (lo < hi) { int m = (lo + hi) >> 1; if (batch[m] < g) lo = m + 1; else hi = m; }
    int st = lo;
    hi = Nn;
    while (lo < hi) { int m = (lo + hi) >> 1; if (batch[m] < g + 1) lo = m + 1; else hi = m; }
    int en = lo;

    float sum = 0.f, mxv = -3.0e38f;
    for (int n = st; n < en; n++) {
        float v = h[(size_t)n * 256 + f];
        sum += v;
        mxv = fmaxf(mxv, v);
    }
    float cnt = (float)(en - st);
    pooled[g * 512 + f]       = sum / fmaxf(cnt, 1.f);
    pooled[g * 512 + 256 + f] = mxv;
}

// ---------------------------------------------------------------------------
// out[g,0:10] = pooled[g,:] @ Wout + bout.  One warp per graph.
// ---------------------------------------------------------------------------
__global__ void k_out(const float* __restrict__ pooled, const float* __restrict__ Wout,
                      const float* __restrict__ bout, float* __restrict__ out) {
    int g = blockIdx.x;
    int lane = threadIdx.x;
    float p[16];
    #pragma unroll
    for (int j = 0; j < 16; j++) p[j] = pooled[g * 512 + j * 32 + lane];
    for (int c = 0; c < 10; c++) {
        float a = 0.f;
        #pragma unroll
        for (int j = 0; j < 16; j++) a += p[j] * Wout[(j * 32 + lane) * 10 + c];
        #pragma unroll
        for (int o = 16; o; o >>= 1) a += __shfl_xor_sync(0xffffffffu, a, o);
        if (lane == 0) out[g * 10 + c] = a + bout[c];
    }
}

// ---------------------------------------------------------------------------
extern "C" void kernel_launch(void* const* d_in, const int* in_sizes, int n_in,
                              void* d_out, int out_size) {
    const float* x    = (const float*)d_in[0];
    const int*   ei   = (const int*)  d_in[1];
    const int*   batch= (const int*)  d_in[2];
    const float* W0   = (const float*)d_in[3];
    const float* as0  = (const float*)d_in[4];
    const float* ad0  = (const float*)d_in[5];
    const float* b0   = (const float*)d_in[6];
    const float* W1   = (const float*)d_in[7];
    const float* as1  = (const float*)d_in[8];
    const float* ad1  = (const float*)d_in[9];
    const float* b1   = (const float*)d_in[10];
    const float* W2   = (const float*)d_in[11];
    const float* as2  = (const float*)d_in[12];
    const float* ad2  = (const float*)d_in[13];
    const float* b2   = (const float*)d_in[14];
    const float* Wout = (const float*)d_in[15];
    const float* bout = (const float*)d_in[16];
    float* out = (float*)d_out;

    int Nn   = in_sizes[2];        // node count (batch_index length)
    int E    = in_sizes[1] / 2;    // edge count
    int Etot = E + Nn;             // + self-loops

    float *P, *Q, *ss, *sd, *mx, *dn, *pl;
    cudaGetSymbolAddress((void**)&P,  g_bufP);
    cudaGetSymbolAddress((void**)&Q,  g_bufQ);
    cudaGetSymbolAddress((void**)&ss, g_ssrc);
    cudaGetSymbolAddress((void**)&sd, g_sdst);
    cudaGetSymbolAddress((void**)&mx, g_max);
    cudaGetSymbolAddress((void**)&dn, g_denom);
    cudaGetSymbolAddress((void**)&pl, g_pooled);

    const int* esrc = ei;
    const int* edst = ei + E;

    struct Layer { const float *W, *as, *ad, *b; int Fin, Fo; };
    Layer L[3] = {
        {W0, as0, ad0, b0, 128, 32},
        {W1, as1, ad1, b1, 128, 64},
        {W2, as2, ad2, b2, 256, 64},
    };

    const float* in = x;
    for (int l = 0; l < 3; l++) {
        int Fin = L[l].Fin, Fo = L[l].Fo, C = Fo * 4;

        dim3 gg(C / 64, (Nn + 63) / 64);
        k_sgemm<<<gg, 256>>>(in, L[l].W, P, Nn, C, Fin);

        int nC4 = Nn * C / 4;
        k_init<<<(nC4 + 255) / 256, 256>>>(Q, dn, mx, nC4, Nn * 4);

        k_scores<<<(Nn * 4 * 32 + 255) / 256, 256>>>(P, L[l].as, L[l].ad, ss, sd, Nn, Fo);

        k_edgemax<<<(Etot + 255) / 256, 256>>>(esrc, edst, ss, sd, mx, E, Etot);

        long long thr = (long long)Etot * 32;
        k_edgeacc<<<(unsigned)((thr + 255) / 256), 256>>>(esrc, edst, ss, sd, mx,
                                                          P, Q, dn, E, Etot, C, Fo);

        k_finalize<<<(Nn * C + 255) / 256, 256>>>(Q, dn, L[l].b, Nn, C, Fo);
        in = Q;
    }

    dim3 pg(128, 2);
    k_pool<<<pg, 128>>>(Q, batch, pl, Nn);
    k_out<<<128, 32>>>(pl, Wout, bout, out);
}

// round 7
// speedup vs baseline: 1.9638x; 1.9638x over previous
#include <cuda_runtime.h>
#include <cstdint>
#include <cstddef>

// ---------------------------------------------------------------------------
// GAT 3-layer + mean/max pool + linear readout, fp32.
// Atomic-free aggregation: build dst-CSR once, then per layer a single
// warp-per-node gather kernel does exp-weighted accumulate + normalize + bias
// + relu in registers (softmax shift-invariance => no max pass needed).
// ---------------------------------------------------------------------------

#define NMAX 50000
#define EMAX 860000
#define GMAX 128

__device__ float g_bufP[NMAX * 256];   // GEMM output h
__device__ float g_bufQ[NMAX * 256];   // aggregated output / next layer input
__device__ float g_ssrc[NMAX * 4];
__device__ float g_sdst[NMAX * 4];
__device__ float g_pooled[GMAX * 512];

__device__ int g_deg[NMAX];
__device__ int g_off[NMAX];
__device__ int g_cur[NMAX];
__device__ int g_csr[EMAX];
__device__ int g_blksum[256];

// ---------------------------------------------------------------------------
// SGEMM: C[M,N] = A[M,K] @ B[K,N], row-major fp32.
// 128x64 block tile, BK=16, 256 threads, 8x4 microtile.
// N,K are multiples of 64/16 here (128 or 256); only M needs guarding.
// ---------------------------------------------------------------------------
__global__ void k_sgemm(const float* __restrict__ A, const float* __restrict__ B,
                        float* __restrict__ C, int M, int N, int K) {
    __shared__ float As[16][128 + 4];   // transposed, +4 pad keeps 16B alignment
    __shared__ float Bs[16][64];
    int tid = threadIdx.x;
    int tx = tid & 15, ty = tid >> 4;
    int rowBase = blockIdx.y * 128;
    int colBase = blockIdx.x * 64;

    int bRow = tid >> 4;
    int bCol = (tid & 15) * 4;

    float acc[8][4] = {};

    for (int k0 = 0; k0 < K; k0 += 16) {
        // Load A tile: 128 rows x 16 k = 512 float4; 2 per thread.
        #pragma unroll
        for (int t = 0; t < 2; t++) {
            int i = tid + t * 256;
            int r = i >> 2;                 // 0..127
            int kg = (i & 3) * 4;           // 0,4,8,12
            float4 av = make_float4(0.f, 0.f, 0.f, 0.f);
            int gr = rowBase + r;
            if (gr < M)
                av = *reinterpret_cast<const float4*>(A + (size_t)gr * K + k0 + kg);
            As[kg + 0][r] = av.x;
            As[kg + 1][r] = av.y;
            As[kg + 2][r] = av.z;
            As[kg + 3][r] = av.w;
        }
        // Load B tile: 16 x 64 = 256 float4; 1 per thread.
        float4 bv = *reinterpret_cast<const float4*>(
            B + (size_t)(k0 + bRow) * N + colBase + bCol);
        *reinterpret_cast<float4*>(&Bs[bRow][bCol]) = bv;
        __syncthreads();

        #pragma unroll
        for (int kk = 0; kk < 16; kk++) {
            float4 ra0 = *reinterpret_cast<const float4*>(&As[kk][ty * 8]);
            float4 ra1 = *reinterpret_cast<const float4*>(&As[kk][ty * 8 + 4]);
            float4 rbv = *reinterpret_cast<const float4*>(&Bs[kk][tx * 4]);
            float ra[8] = {ra0.x, ra0.y, ra0.z, ra0.w, ra1.x, ra1.y, ra1.z, ra1.w};
            float rb[4] = {rbv.x, rbv.y, rbv.z, rbv.w};
            #pragma unroll
            for (int i = 0; i < 8; i++)
                #pragma unroll
                for (int j = 0; j < 4; j++)
                    acc[i][j] += ra[i] * rb[j];
        }
        __syncthreads();
    }

    #pragma unroll
    for (int i = 0; i < 8; i++) {
        int r = rowBase + ty * 8 + i;
        if (r < M) {
            float4 o = make_float4(acc[i][0], acc[i][1], acc[i][2], acc[i][3]);
            *reinterpret_cast<float4*>(C + (size_t)r * N + colBase + tx * 4) = o;
        }
    }
}

// ---------------------------------------------------------------------------
// CSR build: histogram -> 2-level exclusive scan -> scatter.
// ---------------------------------------------------------------------------
__global__ void k_zero_deg(int* __restrict__ deg, int Nn) {
    int i = blockIdx.x * blockDim.x + threadIdx.x;
    if (i < Nn) deg[i] = 0;
}

__global__ void k_hist(const int* __restrict__ edst, int* __restrict__ deg,
                       int E, int Etot) {
    int e = blockIdx.x * blockDim.x + threadIdx.x;
    if (e >= Etot) return;
    int d = (e < E) ? edst[e] : (e - E);
    atomicAdd(deg + d, 1);
}

__global__ void k_scan_local(const int* __restrict__ deg, int* __restrict__ off,
                             int* __restrict__ blksum, int Nn) {
    __shared__ int sh[256];
    int i = blockIdx.x * 256 + threadIdx.x;
    int v = (i < Nn) ? deg[i] : 0;
    sh[threadIdx.x] = v;
    __syncthreads();
    #pragma unroll
    for (int o = 1; o < 256; o <<= 1) {
        int t = (threadIdx.x >= o) ? sh[threadIdx.x - o] : 0;
        __syncthreads();
        sh[threadIdx.x] += t;
        __syncthreads();
    }
    if (i < Nn) off[i] = sh[threadIdx.x] - v;     // exclusive within block
    if (threadIdx.x == 255) blksum[blockIdx.x] = sh[255];
}

__global__ void k_scan_blk(int* __restrict__ blksum, int nb) {
    __shared__ int sh[256];
    int v = (threadIdx.x < nb) ? blksum[threadIdx.x] : 0;
    sh[threadIdx.x] = v;
    __syncthreads();
    #pragma unroll
    for (int o = 1; o < 256; o <<= 1) {
        int t = (threadIdx.x >= o) ? sh[threadIdx.x - o] : 0;
        __syncthreads();
        sh[threadIdx.x] += t;
        __syncthreads();
    }
    if (threadIdx.x < nb) blksum[threadIdx.x] = sh[threadIdx.x] - v;  // exclusive
}

__global__ void k_scan_add(int* __restrict__ off, int* __restrict__ cur,
                           const int* __restrict__ blksum, int Nn) {
    int i = blockIdx.x * blockDim.x + threadIdx.x;
    if (i >= Nn) return;
    int o = off[i] + blksum[i >> 8];
    off[i] = o;
    cur[i] = o;
}

__global__ void k_scatter(const int* __restrict__ esrc, const int* __restrict__ edst,
                          int* __restrict__ cur, int* __restrict__ csr,
                          int E, int Etot) {
    int e = blockIdx.x * blockDim.x + threadIdx.x;
    if (e >= Etot) return;
    int s, d;
    if (e < E) { s = esrc[e]; d = edst[e]; } else { s = d = e - E; }
    int pos = atomicAdd(cur + d, 1);
    csr[pos] = s;
}

// ---------------------------------------------------------------------------
// Per-(node,head) attention scores. Warp per pair.
// ---------------------------------------------------------------------------
__global__ void k_scores(const float* __restrict__ h, const float* __restrict__ asrc,
                         const float* __restrict__ adst, float* __restrict__ ssrc,
                         float* __restrict__ sdst, int Nn, int Fo) {
    int w = (blockIdx.x * blockDim.x + threadIdx.x) >> 5;
    int lane = threadIdx.x & 31;
    if (w >= Nn * 4) return;
    int head = w & 3, node = w >> 2;
    int C = Fo * 4;
    const float* hp = h + (size_t)node * C + head * Fo;
    const float* as = asrc + head * Fo;
    const float* ad = adst + head * Fo;
    float s1 = 0.f, s2 = 0.f;
    for (int f = lane; f < Fo; f += 32) {
        float v = hp[f];
        s1 += v * as[f];
        s2 += v * ad[f];
    }
    #pragma unroll
    for (int o = 16; o; o >>= 1) {
        s1 += __shfl_xor_sync(0xffffffffu, s1, o);
        s2 += __shfl_xor_sync(0xffffffffu, s2, o);
    }
    if (lane == 0) { ssrc[w] = s1; sdst[w] = s2; }
}

// ---------------------------------------------------------------------------
__device__ __forceinline__ float lrelu(float v) { return fmaxf(v, 0.2f * v); }

// ---------------------------------------------------------------------------
// Warp-per-node CSR gather with fused softmax (no max pass: shift-invariant,
// scores are O(1)). Lane covers features c = jj*128 + lane*4 .. +3 (float4).
// out[n] = relu( (sum_e p_e * h[src_e]) / (sum_e p_e + 1e-16) + bias )
// ---------------------------------------------------------------------------
template<int C, int Fo>
__global__ void k_gather(const int* __restrict__ off, const int* __restrict__ deg,
                         const int* __restrict__ csr,
                         const float* __restrict__ ss, const float* __restrict__ sd,
                         const float* __restrict__ h, const float* __restrict__ bias,
                         float* __restrict__ out, int Nn) {
    int w = (blockIdx.x * blockDim.x + threadIdx.x) >> 5;
    int lane = threadIdx.x & 31;
    if (w >= Nn) return;

    constexpr int JJ = C / 128;                 // float4 chunks per lane (1 or 2)
    float4 sdv = *reinterpret_cast<const float4*>(sd + 4 * w);

    float4 acc[JJ];
    #pragma unroll
    for (int j = 0; j < JJ; j++) acc[j] = make_float4(0.f, 0.f, 0.f, 0.f);
    float den0 = 0.f, den1 = 0.f, den2 = 0.f, den3 = 0.f;

    // head index per float4 chunk (uniform within the 4 consecutive features)
    int head[JJ];
    #pragma unroll
    for (int j = 0; j < JJ; j++) head[j] = (j * 128 + lane * 4) / Fo;

    int st = off[w], en = st + deg[w];
    #pragma unroll 2
    for (int k = st; k < en; k++) {
        int s = __ldg(csr + k);
        float4 sv = __ldg(reinterpret_cast<const float4*>(ss + 4 * s));
        float p0 = __expf(lrelu(sv.x + sdv.x));
        float p1 = __expf(lrelu(sv.y + sdv.y));
        float p2 = __expf(lrelu(sv.z + sdv.z));
        float p3 = __expf(lrelu(sv.w + sdv.w));
        den0 += p0; den1 += p1; den2 += p2; den3 += p3;

        const float4* hp = reinterpret_cast<const float4*>(h + (size_t)s * C);
        #pragma unroll
        for (int j = 0; j < JJ; j++) {
            float ph = (head[j] < 2) ? (head[j] == 0 ? p0 : p1)
                                     : (head[j] == 2 ? p2 : p3);
            float4 v = __ldg(hp + j * 32 + lane);
            acc[j].x += ph * v.x;
            acc[j].y += ph * v.y;
            acc[j].z += ph * v.z;
            acc[j].w += ph * v.w;
        }
    }

    float di0 = 1.f / (den0 + 1e-16f);
    float di1 = 1.f / (den1 + 1e-16f);
    float di2 = 1.f / (den2 + 1e-16f);
    float di3 = 1.f / (den3 + 1e-16f);

    #pragma unroll
    for (int j = 0; j < JJ; j++) {
        float di = (head[j] < 2) ? (head[j] == 0 ? di0 : di1)
                                 : (head[j] == 2 ? di2 : di3);
        float4 bv = *reinterpret_cast<const float4*>(bias + j * 128 + lane * 4);
        float4 o;
        o.x = fmaxf(acc[j].x * di + bv.x, 0.f);
        o.y = fmaxf(acc[j].y * di + bv.y, 0.f);
        o.z = fmaxf(acc[j].z * di + bv.z, 0.f);
        o.w = fmaxf(acc[j].w * di + bv.w, 0.f);
        *reinterpret_cast<float4*>(out + (size_t)w * C + j * 128 + lane * 4) = o;
    }
}

// ---------------------------------------------------------------------------
// Per-graph mean/max pool over sorted batch_index.
// ---------------------------------------------------------------------------
__global__ void k_pool(const float* __restrict__ h, const int* __restrict__ batch,
                       float* __restrict__ pooled, int Nn) {
    int g = blockIdx.x;
    int f = blockIdx.y * 128 + threadIdx.x;

    int lo = 0, hi = Nn;
    while (lo < hi) { int m = (lo + hi) >> 1; if (batch[m] < g) lo = m + 1; else hi = m; }
    int st = lo;
    hi = Nn;
    while (lo < hi) { int m = (lo + hi) >> 1; if (batch[m] < g + 1) lo = m + 1; else hi = m; }
    int en = lo;

    float sum = 0.f, mxv = -3.0e38f;
    for (int n = st; n < en; n++) {
        float v = h[(size_t)n * 256 + f];
        sum += v;
        mxv = fmaxf(mxv, v);
    }
    float cnt = (float)(en - st);
    pooled[g * 512 + f]       = sum / fmaxf(cnt, 1.f);
    pooled[g * 512 + 256 + f] = mxv;
}

// ---------------------------------------------------------------------------
__global__ void k_out(const float* __restrict__ pooled, const float* __restrict__ Wout,
                      const float* __restrict__ bout, float* __restrict__ out) {
    int g = blockIdx.x;
    int lane = threadIdx.x;
    float p[16];
    #pragma unroll
    for (int j = 0; j < 16; j++) p[j] = pooled[g * 512 + j * 32 + lane];
    for (int c = 0; c < 10; c++) {
        float a = 0.f;
        #pragma unroll
        for (int j = 0; j < 16; j++) a += p[j] * Wout[(j * 32 + lane) * 10 + c];
        #pragma unroll
        for (int o = 16; o; o >>= 1) a += __shfl_xor_sync(0xffffffffu, a, o);
        if (lane == 0) out[g * 10 + c] = a + bout[c];
    }
}

// ---------------------------------------------------------------------------
extern "C" void kernel_launch(void* const* d_in, const int* in_sizes, int n_in,
                              void* d_out, int out_size) {
    const float* x    = (const float*)d_in[0];
    const int*   ei   = (const int*)  d_in[1];
    const int*   batch= (const int*)  d_in[2];
    const float* W0   = (const float*)d_in[3];
    const float* as0  = (const float*)d_in[4];
    const float* ad0  = (const float*)d_in[5];
    const float* b0   = (const float*)d_in[6];
    const float* W1   = (const float*)d_in[7];
    const float* as1  = (const float*)d_in[8];
    const float* ad1  = (const float*)d_in[9];
    const float* b1   = (const float*)d_in[10];
    const float* W2   = (const float*)d_in[11];
    const float* as2  = (const float*)d_in[12];
    const float* ad2  = (const float*)d_in[13];
    const float* b2   = (const float*)d_in[14];
    const float* Wout = (const float*)d_in[15];
    const float* bout = (const float*)d_in[16];
    float* out = (float*)d_out;

    int Nn   = in_sizes[2];
    int E    = in_sizes[1] / 2;
    int Etot = E + Nn;

    float *P, *Q, *ss, *sd, *pl;
    int *deg, *off, *cur, *csr, *bsum;
    cudaGetSymbolAddress((void**)&P,   g_bufP);
    cudaGetSymbolAddress((void**)&Q,   g_bufQ);
    cudaGetSymbolAddress((void**)&ss,  g_ssrc);
    cudaGetSymbolAddress((void**)&sd,  g_sdst);
    cudaGetSymbolAddress((void**)&pl,  g_pooled);
    cudaGetSymbolAddress((void**)&deg, g_deg);
    cudaGetSymbolAddress((void**)&off, g_off);
    cudaGetSymbolAddress((void**)&cur, g_cur);
    cudaGetSymbolAddress((void**)&csr, g_csr);
    cudaGetSymbolAddress((void**)&bsum,g_blksum);

    const int* esrc = ei;
    const int* edst = ei + E;

    // ---- CSR build (once; shared by all 3 layers) ----
    int nb = (Nn + 255) / 256;
    k_zero_deg<<<nb, 256>>>(deg, Nn);
    k_hist<<<(Etot + 255) / 256, 256>>>(edst, deg, E, Etot);
    k_scan_local<<<nb, 256>>>(deg, off, bsum, Nn);
    k_scan_blk<<<1, 256>>>(bsum, nb);
    k_scan_add<<<nb, 256>>>(off, cur, bsum, Nn);
    k_scatter<<<(Etot + 255) / 256, 256>>>(esrc, edst, cur, csr, E, Etot);

    struct Layer { const float *W, *as, *ad, *b; int Fin, Fo; };
    Layer L[3] = {
        {W0, as0, ad0, b0, 128, 32},
        {W1, as1, ad1, b1, 128, 64},
        {W2, as2, ad2, b2, 256, 64},
    };

    const float* in = x;
    for (int l = 0; l < 3; l++) {
        int Fin = L[l].Fin, Fo = L[l].Fo, C = Fo * 4;

        dim3 gg(C / 64, (Nn + 127) / 128);
        k_sgemm<<<gg, 256>>>(in, L[l].W, P, Nn, C, Fin);

        k_scores<<<(Nn * 4 * 32 + 255) / 256, 256>>>(P, L[l].as, L[l].ad, ss, sd, Nn, Fo);

        int gblocks = (Nn + 7) / 8;   // 8 warps / block
        if (Fo == 32)
            k_gather<128, 32><<<gblocks, 256>>>(off, deg, csr, ss, sd, P, L[l].b, Q, Nn);
        else
            k_gather<256, 64><<<gblocks, 256>>>(off, deg, csr, ss, sd, P, L[l].b, Q, Nn);

        in = Q;
    }

    dim3 pg(128, 2);
    k_pool<<<pg, 128>>>(Q, batch, pl, Nn);
    k_out<<<128, 32>>>(pl, Wout, bout, out);
}

// round 10
// speedup vs baseline: 2.3332x; 1.1881x over previous
#include <cuda_runtime.h>
#include <cstdint>
#include <cstddef>

// ---------------------------------------------------------------------------
// GAT 3-layer + mean/max pool + linear readout.
// GEMMs via tf32 mma.sync tensor cores (fp32 accumulate).
// Aggregation: atomic-free dst-CSR warp-per-node gather with fused softmax.
// ---------------------------------------------------------------------------

#define NMAX 50000
#define EMAX 860000
#define GMAX 128

__device__ float g_bufP[NMAX * 256];   // GEMM output h
__device__ float g_bufQ[NMAX * 256];   // aggregated output / next layer input
__device__ float g_ssrc[NMAX * 4];
__device__ float g_sdst[NMAX * 4];
__device__ float g_pooled[GMAX * 512];

__device__ int g_deg[NMAX];
__device__ int g_off[NMAX];
__device__ int g_cur[NMAX];
__device__ int g_csr[EMAX];
__device__ int g_blksum[256];

// ---------------------------------------------------------------------------
// tf32 tensor-core GEMM: C[M,N] = A[M,K] @ B[K,N], row-major fp32 in/out.
// 128x64 block tile, BK=32, 256 threads = 8 warps, warp tile 64x16.
// SMEM holds operands pre-permuted into m16n8k8 fragment order:
//   As slot = mt*4+kt (mt: m16 tile 0..7, kt: k8 step 0..3), stride 132 words,
//     word = slot*132 + lane*4 + reg   -> mainloop LDS.128, conflict-free.
//   Bs slot = nt*4+kt (nt: n8 tile 0..7), stride 68 words,
//     word = slot*68 + lane*2 + reg    -> mainloop LDS.64, conflict-free.
// Fragment maps (PTX m16n8k8.row.col, verified vs PTX ISA):
//   A: reg = (r16/8) + 2*(c8/4), lane = (r16%8)*4 + (c8%4)
//   B: reg = (k8/4),             lane = n8*4 + (k8%4)
//   C: c0=(r=l/4, c=2*(l%4)) c1=c+1 c2=r+8 c3=r+8,c+1
// ---------------------------------------------------------------------------
__device__ __forceinline__ uint32_t f2tf32(float f) {
    uint32_t u;
    asm("cvt.rna.tf32.f32 %0, %1;" : "=r"(u) : "f"(f));
    return u;
}

__global__ void k_mma(const float* __restrict__ A, const float* __restrict__ B,
                      float* __restrict__ C, int M, int N, int K) {
    __shared__ uint32_t As[32 * 132];   // 16.5 KB
    __shared__ uint32_t Bs[32 * 68];    // 8.5 KB
    int tid  = threadIdx.x;
    int warp = tid >> 5, lane = tid & 31;
    int warpM = warp >> 2, warpN = warp & 3;    // 2 x 4 warp grid
    int rowBase = blockIdx.y * 128;
    int colBase = blockIdx.x * 64;

    float acc[4][2][4];
    #pragma unroll
    for (int mi = 0; mi < 4; mi++)
        #pragma unroll
        for (int ni = 0; ni < 2; ni++)
            #pragma unroll
            for (int r = 0; r < 4; r++) acc[mi][ni][r] = 0.f;

    for (int k0 = 0; k0 < K; k0 += 32) {
        // ---- stage A tile 128x32 into fragment order (4 float4 per thread)
        #pragma unroll
        for (int t = 0; t < 4; t++) {
            int j   = tid + t * 256;        // 0..1023
            int grl = j >> 3;               // row in tile 0..127
            int gc0 = (j & 7) * 4;          // k offset 0,4,..,28
            float4 av = make_float4(0.f, 0.f, 0.f, 0.f);
            int gr = rowBase + grl;
            if (gr < M)
                av = *reinterpret_cast<const float4*>(A + (size_t)gr * K + k0 + gc0);
            int r16  = grl & 15;
            int mt   = grl >> 4;
            int kt   = gc0 >> 3;
            int reg  = (r16 >> 3) + (((gc0 & 7) >> 2) << 1);
            int slot = mt * 4 + kt;
            // lane = (r16%8)*4 + (c%4); c%4 = i for the 4 staged elements
            int base = slot * 132 + ((r16 & 7) * 4) * 4 + reg;
            As[base +  0] = f2tf32(av.x);
            As[base +  4] = f2tf32(av.y);
            As[base +  8] = f2tf32(av.z);
            As[base + 12] = f2tf32(av.w);
        }
        // ---- stage B tile 32x64 into fragment order (2 float4 per thread)
        #pragma unroll
        for (int t = 0; t < 2; t++) {
            int j   = tid + t * 256;        // 0..511
            int gk  = j >> 4;               // k row 0..31
            int gn0 = (j & 15) * 4;         // n offset 0..60
            float4 bv = *reinterpret_cast<const float4*>(
                B + (size_t)(k0 + gk) * N + colBase + gn0);
            int k8   = gk & 7;
            int kt   = gk >> 3;
            int reg  = k8 >> 2;
            int nt   = gn0 >> 3;
            int slot = nt * 4 + kt;
            // lane = n8*4 + (k8%4); n8 = (gn0%8)+i -> word stride 8 per i
            int base = slot * 68 + ((gn0 & 7) * 4 + (k8 & 3)) * 2 + reg;
            Bs[base +  0] = f2tf32(bv.x);
            Bs[base +  8] = f2tf32(bv.y);
            Bs[base + 16] = f2tf32(bv.z);
            Bs[base + 24] = f2tf32(bv.w);
        }
        __syncthreads();

        #pragma unroll
        for (int kt = 0; kt < 4; kt++) {
            uint4 a[4];
            uint2 b[2];
            #pragma unroll
            for (int mi = 0; mi < 4; mi++) {
                int slot = (warpM * 4 + mi) * 4 + kt;
                a[mi] = *reinterpret_cast<const uint4*>(&As[slot * 132 + lane * 4]);
            }
            #pragma unroll
            for (int ni = 0; ni < 2; ni++) {
                int slot = (warpN * 2 + ni) * 4 + kt;
                b[ni] = *reinterpret_cast<const uint2*>(&Bs[slot * 68 + lane * 2]);
            }
            #pragma unroll
            for (int mi = 0; mi < 4; mi++)
                #pragma unroll
                for (int ni = 0; ni < 2; ni++)
                    asm volatile(
                        "mma.sync.aligned.m16n8k8.row.col.f32.tf32.tf32.f32 "
                        "{%0,%1,%2,%3}, {%4,%5,%6,%7}, {%8,%9}, {%0,%1,%2,%3};"
                        : "+f"(acc[mi][ni][0]), "+f"(acc[mi][ni][1]),
                          "+f"(acc[mi][ni][2]), "+f"(acc[mi][ni][3])
                        : "r"(a[mi].x), "r"(a[mi].y), "r"(a[mi].z), "r"(a[mi].w),
                          "r"(b[ni].x), "r"(b[ni].y));
        }
        __syncthreads();
    }

    // ---- epilogue
    int r4 = lane >> 2;
    int c2 = (lane & 3) * 2;
    #pragma unroll
    for (int mi = 0; mi < 4; mi++) {
        #pragma unroll
        for (int ni = 0; ni < 2; ni++) {
            int r0 = rowBase + warpM * 64 + mi * 16 + r4;
            int cc = colBase + warpN * 16 + ni * 8 + c2;
            if (r0 < M)
                *reinterpret_cast<float2*>(C + (size_t)r0 * N + cc) =
                    make_float2(acc[mi][ni][0], acc[mi][ni][1]);
            if (r0 + 8 < M)
                *reinterpret_cast<float2*>(C + (size_t)(r0 + 8) * N + cc) =
                    make_float2(acc[mi][ni][2], acc[mi][ni][3]);
        }
    }
}

// ---------------------------------------------------------------------------
// CSR build: histogram -> 2-level exclusive scan -> scatter.
// ---------------------------------------------------------------------------
__global__ void k_zero_deg(int* __restrict__ deg, int Nn) {
    int i = blockIdx.x * blockDim.x + threadIdx.x;
    if (i < Nn) deg[i] = 0;
}

__global__ void k_hist(const int* __restrict__ edst, int* __restrict__ deg,
                       int E, int Etot) {
    int e = blockIdx.x * blockDim.x + threadIdx.x;
    if (e >= Etot) return;
    int d = (e < E) ? edst[e] : (e - E);
    atomicAdd(deg + d, 1);
}

__global__ void k_scan_local(const int* __restrict__ deg, int* __restrict__ off,
                             int* __restrict__ blksum, int Nn) {
    __shared__ int sh[256];
    int i = blockIdx.x * 256 + threadIdx.x;
    int v = (i < Nn) ? deg[i] : 0;
    sh[threadIdx.x] = v;
    __syncthreads();
    #pragma unroll
    for (int o = 1; o < 256; o <<= 1) {
        int t = (threadIdx.x >= o) ? sh[threadIdx.x - o] : 0;
        __syncthreads();
        sh[threadIdx.x] += t;
        __syncthreads();
    }
    if (i < Nn) off[i] = sh[threadIdx.x] - v;     // exclusive within block
    if (threadIdx.x == 255) blksum[blockIdx.x] = sh[255];
}

__global__ void k_scan_blk(int* __restrict__ blksum, int nb) {
    __shared__ int sh[256];
    int v = (threadIdx.x < nb) ? blksum[threadIdx.x] : 0;
    sh[threadIdx.x] = v;
    __syncthreads();
    #pragma unroll
    for (int o = 1; o < 256; o <<= 1) {
        int t = (threadIdx.x >= o) ? sh[threadIdx.x - o] : 0;
        __syncthreads();
        sh[threadIdx.x] += t;
        __syncthreads();
    }
    if (threadIdx.x < nb) blksum[threadIdx.x] = sh[threadIdx.x] - v;  // exclusive
}

__global__ void k_scan_add(int* __restrict__ off, int* __restrict__ cur,
                           const int* __restrict__ blksum, int Nn) {
    int i = blockIdx.x * blockDim.x + threadIdx.x;
    if (i >= Nn) return;
    int o = off[i] + blksum[i >> 8];
    off[i] = o;
    cur[i] = o;
}

__global__ void k_scatter(const int* __restrict__ esrc, const int* __restrict__ edst,
                          int* __restrict__ cur, int* __restrict__ csr,
                          int E, int Etot) {
    int e = blockIdx.x * blockDim.x + threadIdx.x;
    if (e >= Etot) return;
    int s, d;
    if (e < E) { s = esrc[e]; d = edst[e]; } else { s = d = e - E; }
    int pos = atomicAdd(cur + d, 1);
    csr[pos] = s;
}

// ---------------------------------------------------------------------------
// Per-(node,head) attention scores. Warp per pair.
// ---------------------------------------------------------------------------
__global__ void k_scores(const float* __restrict__ h, const float* __restrict__ asrc,
                         const float* __restrict__ adst, float* __restrict__ ssrc,
                         float* __restrict__ sdst, int Nn, int Fo) {
    int w = (blockIdx.x * blockDim.x + threadIdx.x) >> 5;
    int lane = threadIdx.x & 31;
    if (w >= Nn * 4) return;
    int head = w & 3, node = w >> 2;
    int C = Fo * 4;
    const float* hp = h + (size_t)node * C + head * Fo;
    const float* as = asrc + head * Fo;
    const float* ad = adst + head * Fo;
    float s1 = 0.f, s2 = 0.f;
    for (int f = lane; f < Fo; f += 32) {
        float v = hp[f];
        s1 += v * as[f];
        s2 += v * ad[f];
    }
    #pragma unroll
    for (int o = 16; o; o >>= 1) {
        s1 += __shfl_xor_sync(0xffffffffu, s1, o);
        s2 += __shfl_xor_sync(0xffffffffu, s2, o);
    }
    if (lane == 0) { ssrc[w] = s1; sdst[w] = s2; }
}

// ---------------------------------------------------------------------------
__device__ __forceinline__ float lrelu(float v) { return fmaxf(v, 0.2f * v); }

// ---------------------------------------------------------------------------
// Warp-per-node CSR gather with fused softmax (no max pass: shift-invariant,
// scores are O(1)). Lane covers features c = jj*128 + lane*4 .. +3 (float4).
// out[n] = relu( (sum_e p_e * h[src_e]) / (sum_e p_e + 1e-16) + bias )
// ---------------------------------------------------------------------------
template<int C, int Fo>
__global__ void k_gather(const int* __restrict__ off, const int* __restrict__ deg,
                         const int* __restrict__ csr,
                         const float* __restrict__ ss, const float* __restrict__ sd,
                         const float* __restrict__ h, const float* __restrict__ bias,
                         float* __restrict__ out, int Nn) {
    int w = (blockIdx.x * blockDim.x + threadIdx.x) >> 5;
    int lane = threadIdx.x & 31;
    if (w >= Nn) return;

    constexpr int JJ = C / 128;                 // float4 chunks per lane (1 or 2)
    float4 sdv = *reinterpret_cast<const float4*>(sd + 4 * w);

    float4 acc[JJ];
    #pragma unroll
    for (int j = 0; j < JJ; j++) acc[j] = make_float4(0.f, 0.f, 0.f, 0.f);
    float den0 = 0.f, den1 = 0.f, den2 = 0.f, den3 = 0.f;

    // head index per float4 chunk (uniform within the 4 consecutive features)
    int head[JJ];
    #pragma unroll
    for (int j = 0; j < JJ; j++) head[j] = (j * 128 + lane * 4) / Fo;

    int st = off[w], en = st + deg[w];
    #pragma unroll 2
    for (int k = st; k < en; k++) {
        int s = __ldg(csr + k);
        float4 sv = __ldg(reinterpret_cast<const float4*>(ss + 4 * s));
        float p0 = __expf(lrelu(sv.x + sdv.x));
        float p1 = __expf(lrelu(sv.y + sdv.y));
        float p2 = __expf(lrelu(sv.z + sdv.z));
        float p3 = __expf(lrelu(sv.w + sdv.w));
        den0 += p0; den1 += p1; den2 += p2; den3 += p3;

        const float4* hp = reinterpret_cast<const float4*>(h + (size_t)s * C);
        #pragma unroll
        for (int j = 0; j < JJ; j++) {
            float ph = (head[j] < 2) ? (head[j] == 0 ? p0 : p1)
                                     : (head[j] == 2 ? p2 : p3);
            float4 v = __ldg(hp + j * 32 + lane);
            acc[j].x += ph * v.x;
            acc[j].y += ph * v.y;
            acc[j].z += ph * v.z;
            acc[j].w += ph * v.w;
        }
    }

    float di0 = 1.f / (den0 + 1e-16f);
    float di1 = 1.f / (den1 + 1e-16f);
    float di2 = 1.f / (den2 + 1e-16f);
    float di3 = 1.f / (den3 + 1e-16f);

    #pragma unroll
    for (int j = 0; j < JJ; j++) {
        float di = (head[j] < 2) ? (head[j] == 0 ? di0 : di1)
                                 : (head[j] == 2 ? di2 : di3);
        float4 bv = *reinterpret_cast<const float4*>(bias + j * 128 + lane * 4);
        float4 o;
        o.x = fmaxf(acc[j].x * di + bv.x, 0.f);
        o.y = fmaxf(acc[j].y * di + bv.y, 0.f);
        o.z = fmaxf(acc[j].z * di + bv.z, 0.f);
        o.w = fmaxf(acc[j].w * di + bv.w, 0.f);
        *reinterpret_cast<float4*>(out + (size_t)w * C + j * 128 + lane * 4) = o;
    }
}

// ---------------------------------------------------------------------------
// Per-graph mean/max pool over sorted batch_index.
// ---------------------------------------------------------------------------
__global__ void k_pool(const float* __restrict__ h, const int* __restrict__ batch,
                       float* __restrict__ pooled, int Nn) {
    int g = blockIdx.x;
    int f = blockIdx.y * 128 + threadIdx.x;

    int lo = 0, hi = Nn;
    while (lo < hi) { int m = (lo + hi) >> 1; if (batch[m] < g) lo = m + 1; else hi = m; }
    int st = lo;
    hi = Nn;
    while (lo < hi) { int m = (lo + hi) >> 1; if (batch[m] < g + 1) lo = m + 1; else hi = m; }
    int en = lo;

    float sum = 0.f, mxv = -3.0e38f;
    for (int n = st; n < en; n++) {
        float v = h[(size_t)n * 256 + f];
        sum += v;
        mxv = fmaxf(mxv, v);
    }
    float cnt = (float)(en - st);
    pooled[g * 512 + f]       = sum / fmaxf(cnt, 1.f);
    pooled[g * 512 + 256 + f] = mxv;
}

// ---------------------------------------------------------------------------
__global__ void k_out(const float* __restrict__ pooled, const float* __restrict__ Wout,
                      const float* __restrict__ bout, float* __restrict__ out) {
    int g = blockIdx.x;
    int lane = threadIdx.x;
    float p[16];
    #pragma unroll
    for (int j = 0; j < 16; j++) p[j] = pooled[g * 512 + j * 32 + lane];
    for (int c = 0; c < 10; c++) {
        float a = 0.f;
        #pragma unroll
        for (int j = 0; j < 16; j++) a += p[j] * Wout[(j * 32 + lane) * 10 + c];
        #pragma unroll
        for (int o = 16; o; o >>= 1) a += __shfl_xor_sync(0xffffffffu, a, o);
        if (lane == 0) out[g * 10 + c] = a + bout[c];
    }
}

// ---------------------------------------------------------------------------
extern "C" void kernel_launch(void* const* d_in, const int* in_sizes, int n_in,
                              void* d_out, int out_size) {
    const float* x    = (const float*)d_in[0];
    const int*   ei   = (const int*)  d_in[1];
    const int*   batch= (const int*)  d_in[2];
    const float* W0   = (const float*)d_in[3];
    const float* as0  = (const float*)d_in[4];
    const float* ad0  = (const float*)d_in[5];
    const float* b0   = (const float*)d_in[6];
    const float* W1   = (const float*)d_in[7];
    const float* as1  = (const float*)d_in[8];
    const float* ad1  = (const float*)d_in[9];
    const float* b1   = (const float*)d_in[10];
    const float* W2   = (const float*)d_in[11];
    const float* as2  = (const float*)d_in[12];
    const float* ad2  = (const float*)d_in[13];
    const float* b2   = (const float*)d_in[14];
    const float* Wout = (const float*)d_in[15];
    const float* bout = (const float*)d_in[16];
    float* out = (float*)d_out;

    int Nn   = in_sizes[2];
    int E    = in_sizes[1] / 2;
    int Etot = E + Nn;

    float *P, *Q, *ss, *sd, *pl;
    int *deg, *off, *cur, *csr, *bsum;
    cudaGetSymbolAddress((void**)&P,   g_bufP);
    cudaGetSymbolAddress((void**)&Q,   g_bufQ);
    cudaGetSymbolAddress((void**)&ss,  g_ssrc);
    cudaGetSymbolAddress((void**)&sd,  g_sdst);
    cudaGetSymbolAddress((void**)&pl,  g_pooled);
    cudaGetSymbolAddress((void**)&deg, g_deg);
    cudaGetSymbolAddress((void**)&off, g_off);
    cudaGetSymbolAddress((void**)&cur, g_cur);
    cudaGetSymbolAddress((void**)&csr, g_csr);
    cudaGetSymbolAddress((void**)&bsum,g_blksum);

    const int* esrc = ei;
    const int* edst = ei + E;

    // ---- CSR build (once; shared by all 3 layers) ----
    int nb = (Nn + 255) / 256;
    k_zero_deg<<<nb, 256>>>(deg, Nn);
    k_hist<<<(Etot + 255) / 256, 256>>>(edst, deg, E, Etot);
    k_scan_local<<<nb, 256>>>(deg, off, bsum, Nn);
    k_scan_blk<<<1, 256>>>(bsum, nb);
    k_scan_add<<<nb, 256>>>(off, cur, bsum, Nn);
    k_scatter<<<(Etot + 255) / 256, 256>>>(esrc, edst, cur, csr, E, Etot);

    struct Layer { const float *W, *as, *ad, *b; int Fin, Fo; };
    Layer L[3] = {
        {W0, as0, ad0, b0, 128, 32},
        {W1, as1, ad1, b1, 128, 64},
        {W2, as2, ad2, b2, 256, 64},
    };

    const float* in = x;
    for (int l = 0; l < 3; l++) {
        int Fin = L[l].Fin, Fo = L[l].Fo, C = Fo * 4;

        dim3 gg(C / 64, (Nn + 127) / 128);
        k_mma<<<gg, 256>>>(in, L[l].W, P, Nn, C, Fin);

        k_scores<<<(Nn * 4 * 32 + 255) / 256, 256>>>(P, L[l].as, L[l].ad, ss, sd, Nn, Fo);

        int gblocks = (Nn + 7) / 8;   // 8 warps / block
        if (Fo == 32)
            k_gather<128, 32><<<gblocks, 256>>>(off, deg, csr, ss, sd, P, L[l].b, Q, Nn);
        else
            k_gather<256, 64><<<gblocks, 256>>>(off, deg, csr, ss, sd, P, L[l].b, Q, Nn);

        in = Q;
    }

    dim3 pg(128, 2);
    k_pool<<<pg, 128>>>(Q, batch, pl, Nn);
    k_out<<<128, 32>>>(pl, Wout, bout, out);
}

// round 14
// speedup vs baseline: 2.3726x; 1.0169x over previous
#include <cuda_runtime.h>
#include <cstdint>
#include <cstddef>

// ---------------------------------------------------------------------------
// GAT 3-layer + mean/max pool + linear readout.
// GEMMs via tf32 mma.sync tensor cores (fp32 accumulate), double-buffered
// smem pipeline (1 sync/iter, gmem prefetch overlapped with mma).
// Aggregation: atomic-free dst-CSR warp-per-node gather with fused softmax.
// ---------------------------------------------------------------------------

#define NMAX 50000
#define EMAX 860000
#define GMAX 128

__device__ float g_bufP[NMAX * 256];   // GEMM output h
__device__ float g_bufQ[NMAX * 256];   // aggregated output / next layer input
__device__ float g_ssrc[NMAX * 4];
__device__ float g_sdst[NMAX * 4];
__device__ float g_pooled[GMAX * 512];

__device__ int g_deg[NMAX];
__device__ int g_off[NMAX];
__device__ int g_cur[NMAX];
__device__ int g_csr[EMAX];
__device__ int g_blksum[256];

// ---------------------------------------------------------------------------
// tf32 tensor-core GEMM: C[M,N] = A[M,K] @ B[K,N], row-major fp32 in/out.
// 128x64 block tile, BK=32, 256 threads = 8 warps, warp tile 64x16.
// Double-buffered: store tile -> sync -> prefetch next tile (regs) -> compute.
// SMEM holds operands pre-permuted into m16n8k8 fragment order:
//   As slot = mt*4+kt, stride 132 words: word = slot*132 + lane*4 + reg
//   Bs slot = nt*4+kt, stride 68 words:  word = slot*68  + lane*2 + reg
// Fragment maps (PTX m16n8k8.row.col):
//   A: reg = (r16/8) + 2*(c8/4), lane = (r16%8)*4 + (c8%4)
//   B: reg = (k8/4),             lane = n8*4 + (k8%4)
//   C: c0=(r=l/4, c=2*(l%4)) c1=c+1 c2=r+8 c3=r+8,c+1
// ---------------------------------------------------------------------------
__device__ __forceinline__ uint32_t f2tf32(float f) {
    uint32_t u;
    asm("cvt.rna.tf32.f32 %0, %1;" : "=r"(u) : "f"(f));
    return u;
}

__global__ void k_mma(const float* __restrict__ A, const float* __restrict__ B,
                      float* __restrict__ C, int M, int N, int K) {
    __shared__ uint32_t As[2][32 * 132];   // 2 x 16.5 KB
    __shared__ uint32_t Bs[2][32 * 68];    // 2 x 8.5 KB
    int tid  = threadIdx.x;
    int warp = tid >> 5, lane = tid & 31;
    int warpM = warp >> 2, warpN = warp & 3;    // 2 x 4 warp grid
    int rowBase = blockIdx.y * 128;
    int colBase = blockIdx.x * 64;

    // Per-thread staging addresses (constant across iters).
    // A: 4 chunks, j = tid + t*256
    int aRowL[4], aBase[4];
    #pragma unroll
    for (int t = 0; t < 4; t++) {
        int j   = tid + t * 256;
        int grl = j >> 3;
        int gc0 = (j & 7) * 4;
        aRowL[t] = grl;
        int r16  = grl & 15;
        int mt   = grl >> 4;
        int kt   = gc0 >> 3;
        int reg  = (r16 >> 3) + (((gc0 & 7) >> 2) << 1);
        aBase[t] = (mt * 4 + kt) * 132 + ((r16 & 7) * 4) * 4 + reg;
    }
    int aCol0[4];
    #pragma unroll
    for (int t = 0; t < 4; t++) aCol0[t] = ((tid + t * 256) & 7) * 4;

    // B: 2 chunks
    int bRowK[2], bCol0[2], bBase[2];
    #pragma unroll
    for (int t = 0; t < 2; t++) {
        int j   = tid + t * 256;
        int gk  = j >> 4;
        int gn0 = (j & 15) * 4;
        bRowK[t] = gk;
        bCol0[t] = gn0;
        int k8   = gk & 7;
        int kt   = gk >> 3;
        int reg  = k8 >> 2;
        int nt   = gn0 >> 3;
        bBase[t] = (nt * 4 + kt) * 68 + ((gn0 & 7) * 4 + (k8 & 3)) * 2 + reg;
    }

    float acc[4][2][4];
    #pragma unroll
    for (int mi = 0; mi < 4; mi++)
        #pragma unroll
        for (int ni = 0; ni < 2; ni++)
            #pragma unroll
            for (int r = 0; r < 4; r++) acc[mi][ni][r] = 0.f;

    float4 avr[4], bvr[2];

    // prefetch k0 = 0
    #pragma unroll
    for (int t = 0; t < 4; t++) {
        int gr = rowBase + aRowL[t];
        avr[t] = make_float4(0.f, 0.f, 0.f, 0.f);
        if (gr < M)
            avr[t] = *reinterpret_cast<const float4*>(A + (size_t)gr * K + aCol0[t]);
    }
    #pragma unroll
    for (int t = 0; t < 2; t++)
        bvr[t] = *reinterpret_cast<const float4*>(
            B + (size_t)bRowK[t] * N + colBase + bCol0[t]);

    int p = 0;
    for (int k0 = 0; k0 < K; k0 += 32) {
        // ---- store staged regs into buffer p
        #pragma unroll
        for (int t = 0; t < 4; t++) {
            uint32_t* dst = &As[p][aBase[t]];
            dst[ 0] = f2tf32(avr[t].x);
            dst[ 4] = f2tf32(avr[t].y);
            dst[ 8] = f2tf32(avr[t].z);
            dst[12] = f2tf32(avr[t].w);
        }
        #pragma unroll
        for (int t = 0; t < 2; t++) {
            uint32_t* dst = &Bs[p][bBase[t]];
            dst[ 0] = f2tf32(bvr[t].x);
            dst[ 8] = f2tf32(bvr[t].y);
            dst[16] = f2tf32(bvr[t].z);
            dst[24] = f2tf32(bvr[t].w);
        }
        __syncthreads();

        // ---- prefetch next tile into regs (overlaps with compute below)
        int kn = k0 + 32;
        if (kn < K) {
            #pragma unroll
            for (int t = 0; t < 4; t++) {
                int gr = rowBase + aRowL[t];
                avr[t] = make_float4(0.f, 0.f, 0.f, 0.f);
                if (gr < M)
                    avr[t] = *reinterpret_cast<const float4*>(
                        A + (size_t)gr * K + kn + aCol0[t]);
            }
            #pragma unroll
            for (int t = 0; t < 2; t++)
                bvr[t] = *reinterpret_cast<const float4*>(
                    B + (size_t)(kn + bRowK[t]) * N + colBase + bCol0[t]);
        }

        // ---- compute from buffer p
        #pragma unroll
        for (int kt = 0; kt < 4; kt++) {
            uint4 a[4];
            uint2 b[2];
            #pragma unroll
            for (int mi = 0; mi < 4; mi++) {
                int slot = (warpM * 4 + mi) * 4 + kt;
                a[mi] = *reinterpret_cast<const uint4*>(&As[p][slot * 132 + lane * 4]);
            }
            #pragma unroll
            for (int ni = 0; ni < 2; ni++) {
                int slot = (warpN * 2 + ni) * 4 + kt;
                b[ni] = *reinterpret_cast<const uint2*>(&Bs[p][slot * 68 + lane * 2]);
            }
            #pragma unroll
            for (int mi = 0; mi < 4; mi++)
                #pragma unroll
                for (int ni = 0; ni < 2; ni++)
                    asm volatile(
                        "mma.sync.aligned.m16n8k8.row.col.f32.tf32.tf32.f32 "
                        "{%0,%1,%2,%3}, {%4,%5,%6,%7}, {%8,%9}, {%0,%1,%2,%3};"
                        : "+f"(acc[mi][ni][0]), "+f"(acc[mi][ni][1]),
                          "+f"(acc[mi][ni][2]), "+f"(acc[mi][ni][3])
                        : "r"(a[mi].x), "r"(a[mi].y), "r"(a[mi].z), "r"(a[mi].w),
                          "r"(b[ni].x), "r"(b[ni].y));
        }
        p ^= 1;
    }

    // ---- epilogue
    int r4 = lane >> 2;
    int c2 = (lane & 3) * 2;
    #pragma unroll
    for (int mi = 0; mi < 4; mi++) {
        #pragma unroll
        for (int ni = 0; ni < 2; ni++) {
            int r0 = rowBase + warpM * 64 + mi * 16 + r4;
            int cc = colBase + warpN * 16 + ni * 8 + c2;
            if (r0 < M)
                *reinterpret_cast<float2*>(C + (size_t)r0 * N + cc) =
                    make_float2(acc[mi][ni][0], acc[mi][ni][1]);
            if (r0 + 8 < M)
                *reinterpret_cast<float2*>(C + (size_t)(r0 + 8) * N + cc) =
                    make_float2(acc[mi][ni][2], acc[mi][ni][3]);
        }
    }
}

// ---------------------------------------------------------------------------
// CSR build: histogram -> 2-level exclusive scan -> scatter.
// ---------------------------------------------------------------------------
__global__ void k_zero_deg(int* __restrict__ deg, int Nn) {
    int i = blockIdx.x * blockDim.x + threadIdx.x;
    if (i < Nn) deg[i] = 0;
}

__global__ void k_hist(const int* __restrict__ edst, int* __restrict__ deg,
                       int E, int Etot) {
    int e = blockIdx.x * blockDim.x + threadIdx.x;
    if (e >= Etot) return;
    int d = (e < E) ? edst[e] : (e - E);
    atomicAdd(deg + d, 1);
}

__global__ void k_scan_local(const int* __restrict__ deg, int* __restrict__ off,
                             int* __restrict__ blksum, int Nn) {
    __shared__ int sh[256];
    int i = blockIdx.x * 256 + threadIdx.x;
    int v = (i < Nn) ? deg[i] : 0;
    sh[threadIdx.x] = v;
    __syncthreads();
    #pragma unroll
    for (int o = 1; o < 256; o <<= 1) {
        int t = (threadIdx.x >= o) ? sh[threadIdx.x - o] : 0;
        __syncthreads();
        sh[threadIdx.x] += t;
        __syncthreads();
    }
    if (i < Nn) off[i] = sh[threadIdx.x] - v;     // exclusive within block
    if (threadIdx.x == 255) blksum[blockIdx.x] = sh[255];
}

__global__ void k_scan_blk(int* __restrict__ blksum, int nb) {
    __shared__ int sh[256];
    int v = (threadIdx.x < nb) ? blksum[threadIdx.x] : 0;
    sh[threadIdx.x] = v;
    __syncthreads();
    #pragma unroll
    for (int o = 1; o < 256; o <<= 1) {
        int t = (threadIdx.x >= o) ? sh[threadIdx.x - o] : 0;
        __syncthreads();
        sh[threadIdx.x] += t;
        __syncthreads();
    }
    if (threadIdx.x < nb) blksum[threadIdx.x] = sh[threadIdx.x] - v;  // exclusive
}

__global__ void k_scan_add(int* __restrict__ off, int* __restrict__ cur,
                           const int* __restrict__ blksum, int Nn) {
    int i = blockIdx.x * blockDim.x + threadIdx.x;
    if (i >= Nn) return;
    int o = off[i] + blksum[i >> 8];
    off[i] = o;
    cur[i] = o;
}

__global__ void k_scatter(const int* __restrict__ esrc, const int* __restrict__ edst,
                          int* __restrict__ cur, int* __restrict__ csr,
                          int E, int Etot) {
    int e = blockIdx.x * blockDim.x + threadIdx.x;
    if (e >= Etot) return;
    int s, d;
    if (e < E) { s = esrc[e]; d = edst[e]; } else { s = d = e - E; }
    int pos = atomicAdd(cur + d, 1);
    csr[pos] = s;
}

// ---------------------------------------------------------------------------
// Per-(node,head) attention scores. Warp per pair.
// ---------------------------------------------------------------------------
__global__ void k_scores(const float* __restrict__ h, const float* __restrict__ asrc,
                         const float* __restrict__ adst, float* __restrict__ ssrc,
                         float* __restrict__ sdst, int Nn, int Fo) {
    int w = (blockIdx.x * blockDim.x + threadIdx.x) >> 5;
    int lane = threadIdx.x & 31;
    if (w >= Nn * 4) return;
    int head = w & 3, node = w >> 2;
    int C = Fo * 4;
    const float* hp = h + (size_t)node * C + head * Fo;
    const float* as = asrc + head * Fo;
    const float* ad = adst + head * Fo;
    float s1 = 0.f, s2 = 0.f;
    for (int f = lane; f < Fo; f += 32) {
        float v = hp[f];
        s1 += v * as[f];
        s2 += v * ad[f];
    }
    #pragma unroll
    for (int o = 16; o; o >>= 1) {
        s1 += __shfl_xor_sync(0xffffffffu, s1, o);
        s2 += __shfl_xor_sync(0xffffffffu, s2, o);
    }
    if (lane == 0) { ssrc[w] = s1; sdst[w] = s2; }
}

// ---------------------------------------------------------------------------
__device__ __forceinline__ float lrelu(float v) { return fmaxf(v, 0.2f * v); }

// ---------------------------------------------------------------------------
// Warp-per-node CSR gather with fused softmax (no max pass: shift-invariant,
// scores are O(1)). Lane covers features c = jj*128 + lane*4 .. +3 (float4).
// out[n] = relu( (sum_e p_e * h[src_e]) / (sum_e p_e + 1e-16) + bias )
// ---------------------------------------------------------------------------
template<int C, int Fo>
__global__ void k_gather(const int* __restrict__ off, const int* __restrict__ deg,
                         const int* __restrict__ csr,
                         const float* __restrict__ ss, const float* __restrict__ sd,
                         const float* __restrict__ h, const float* __restrict__ bias,
                         float* __restrict__ out, int Nn) {
    int w = (blockIdx.x * blockDim.x + threadIdx.x) >> 5;
    int lane = threadIdx.x & 31;
    if (w >= Nn) return;

    constexpr int JJ = C / 128;                 // float4 chunks per lane (1 or 2)
    float4 sdv = *reinterpret_cast<const float4*>(sd + 4 * w);

    float4 acc[JJ];
    #pragma unroll
    for (int j = 0; j < JJ; j++) acc[j] = make_float4(0.f, 0.f, 0.f, 0.f);
    float den0 = 0.f, den1 = 0.f, den2 = 0.f, den3 = 0.f;

    // head index per float4 chunk (uniform within the 4 consecutive features)
    int head[JJ];
    #pragma unroll
    for (int j = 0; j < JJ; j++) head[j] = (j * 128 + lane * 4) / Fo;

    int st = off[w], en = st + deg[w];
    #pragma unroll 2
    for (int k = st; k < en; k++) {
        int s = __ldg(csr + k);
        float4 sv = __ldg(reinterpret_cast<const float4*>(ss + 4 * s));
        float p0 = __expf(lrelu(sv.x + sdv.x));
        float p1 = __expf(lrelu(sv.y + sdv.y));
        float p2 = __expf(lrelu(sv.z + sdv.z));
        float p3 = __expf(lrelu(sv.w + sdv.w));
        den0 += p0; den1 += p1; den2 += p2; den3 += p3;

        const float4* hp = reinterpret_cast<const float4*>(h + (size_t)s * C);
        #pragma unroll
        for (int j = 0; j < JJ; j++) {
            float ph = (head[j] < 2) ? (head[j] == 0 ? p0 : p1)
                                     : (head[j] == 2 ? p2 : p3);
            float4 v = __ldg(hp + j * 32 + lane);
            acc[j].x += ph * v.x;
            acc[j].y += ph * v.y;
            acc[j].z += ph * v.z;
            acc[j].w += ph * v.w;
        }
    }

    float di0 = 1.f / (den0 + 1e-16f);
    float di1 = 1.f / (den1 + 1e-16f);
    float di2 = 1.f / (den2 + 1e-16f);
    float di3 = 1.f / (den3 + 1e-16f);

    #pragma unroll
    for (int j = 0; j < JJ; j++) {
        float di = (head[j] < 2) ? (head[j] == 0 ? di0 : di1)
                                 : (head[j] == 2 ? di2 : di3);
        float4 bv = *reinterpret_cast<const float4*>(bias + j * 128 + lane * 4);
        float4 o;
        o.x = fmaxf(acc[j].x * di + bv.x, 0.f);
        o.y = fmaxf(acc[j].y * di + bv.y, 0.f);
        o.z = fmaxf(acc[j].z * di + bv.z, 0.f);
        o.w = fmaxf(acc[j].w * di + bv.w, 0.f);
        *reinterpret_cast<float4*>(out + (size_t)w * C + j * 128 + lane * 4) = o;
    }
}

// ---------------------------------------------------------------------------
// Per-graph mean/max pool over sorted batch_index.
// ---------------------------------------------------------------------------
__global__ void k_pool(const float* __restrict__ h, const int* __restrict__ batch,
                       float* __restrict__ pooled, int Nn) {
    int g = blockIdx.x;
    int f = blockIdx.y * 128 + threadIdx.x;

    int lo = 0, hi = Nn;
    while (lo < hi) { int m = (lo + hi) >> 1; if (batch[m] < g) lo = m + 1; else hi = m; }
    int st = lo;
    hi = Nn;
    while (lo < hi) { int m = (lo + hi) >> 1; if (batch[m] < g + 1) lo = m + 1; else hi = m; }
    int en = lo;

    float sum = 0.f, mxv = -3.0e38f;
    for (int n = st; n < en; n++) {
        float v = h[(size_t)n * 256 + f];
        sum += v;
        mxv = fmaxf(mxv, v);
    }
    float cnt = (float)(en - st);
    pooled[g * 512 + f]       = sum / fmaxf(cnt, 1.f);
    pooled[g * 512 + 256 + f] = mxv;
}

// ---------------------------------------------------------------------------
__global__ void k_out(const float* __restrict__ pooled, const float* __restrict__ Wout,
                      const float* __restrict__ bout, float* __restrict__ out) {
    int g = blockIdx.x;
    int lane = threadIdx.x;
    float p[16];
    #pragma unroll
    for (int j = 0; j < 16; j++) p[j] = pooled[g * 512 + j * 32 + lane];
    for (int c = 0; c < 10; c++) {
        float a = 0.f;
        #pragma unroll
        for (int j = 0; j < 16; j++) a += p[j] * Wout[(j * 32 + lane) * 10 + c];
        #pragma unroll
        for (int o = 16; o; o >>= 1) a += __shfl_xor_sync(0xffffffffu, a, o);
        if (lane == 0) out[g * 10 + c] = a + bout[c];
    }
}

// ---------------------------------------------------------------------------
extern "C" void kernel_launch(void* const* d_in, const int* in_sizes, int n_in,
                              void* d_out, int out_size) {
    const float* x    = (const float*)d_in[0];
    const int*   ei   = (const int*)  d_in[1];
    const int*   batch= (const int*)  d_in[2];
    const float* W0   = (const float*)d_in[3];
    const float* as0  = (const float*)d_in[4];
    const float* ad0  = (const float*)d_in[5];
    const float* b0   = (const float*)d_in[6];
    const float* W1   = (const float*)d_in[7];
    const float* as1  = (const float*)d_in[8];
    const float* ad1  = (const float*)d_in[9];
    const float* b1   = (const float*)d_in[10];
    const float* W2   = (const float*)d_in[11];
    const float* as2  = (const float*)d_in[12];
    const float* ad2  = (const float*)d_in[13];
    const float* b2   = (const float*)d_in[14];
    const float* Wout = (const float*)d_in[15];
    const float* bout = (const float*)d_in[16];
    float* out = (float*)d_out;

    int Nn   = in_sizes[2];
    int E    = in_sizes[1] / 2;
    int Etot = E + Nn;

    float *P, *Q, *ss, *sd, *pl;
    int *deg, *off, *cur, *csr, *bsum;
    cudaGetSymbolAddress((void**)&P,   g_bufP);
    cudaGetSymbolAddress((void**)&Q,   g_bufQ);
    cudaGetSymbolAddress((void**)&ss,  g_ssrc);
    cudaGetSymbolAddress((void**)&sd,  g_sdst);
    cudaGetSymbolAddress((void**)&pl,  g_pooled);
    cudaGetSymbolAddress((void**)&deg, g_deg);
    cudaGetSymbolAddress((void**)&off, g_off);
    cudaGetSymbolAddress((void**)&cur, g_cur);
    cudaGetSymbolAddress((void**)&csr, g_csr);
    cudaGetSymbolAddress((void**)&bsum,g_blksum);

    const int* esrc = ei;
    const int* edst = ei + E;

    // ---- CSR build (once; shared by all 3 layers) ----
    int nb = (Nn + 255) / 256;
    k_zero_deg<<<nb, 256>>>(deg, Nn);
    k_hist<<<(Etot + 255) / 256, 256>>>(edst, deg, E, Etot);
    k_scan_local<<<nb, 256>>>(deg, off, bsum, Nn);
    k_scan_blk<<<1, 256>>>(bsum, nb);
    k_scan_add<<<nb, 256>>>(off, cur, bsum, Nn);
    k_scatter<<<(Etot + 255) / 256, 256>>>(esrc, edst, cur, csr, E, Etot);

    struct Layer { const float *W, *as, *ad, *b; int Fin, Fo; };
    Layer L[3] = {
        {W0, as0, ad0, b0, 128, 32},
        {W1, as1, ad1, b1, 128, 64},
        {W2, as2, ad2, b2, 256, 64},
    };

    const float* in = x;
    for (int l = 0; l < 3; l++) {
        int Fin = L[l].Fin, Fo = L[l].Fo, C = Fo * 4;

        dim3 gg(C / 64, (Nn + 127) / 128);
        k_mma<<<gg, 256>>>(in, L[l].W, P, Nn, C, Fin);

        k_scores<<<(Nn * 4 * 32 + 255) / 256, 256>>>(P, L[l].as, L[l].ad, ss, sd, Nn, Fo);

        int gblocks = (Nn + 7) / 8;   // 8 warps / block
        if (Fo == 32)
            k_gather<128, 32><<<gblocks, 256>>>(off, deg, csr, ss, sd, P, L[l].b, Q, Nn);
        else
            k_gather<256, 64><<<gblocks, 256>>>(off, deg, csr, ss, sd, P, L[l].b, Q, Nn);

        in = Q;
    }

    dim3 pg(128, 2);
    k_pool<<<pg, 128>>>(Q, batch, pl, Nn);
    k_out<<<128, 32>>>(pl, Wout, bout, out);
}